// round 9
// baseline (speedup 1.0000x reference)
#include <cuda_runtime.h>

// Fixed problem shapes
#define DIMD 272
#define NC   19
#define WCOLS 20                 // padded W cols (10 f32x2 pairs)
#define NPAIR 10
#define ZROWF 32                 // Z row stride floats = 128 B
#define NROWS 65536
#define NISEG 4096
#define THREADS 256
#define PB_ROWS 512              // rows per proj block (2 per thread)
#define PROJ_BLOCKS (NROWS / PB_ROWS)   // 128
#define SDW 16                   // d's per stage (272 = 17*16)
#define NSTAGE 17
#define XST 80                   // stage row stride bytes (64 data + 16 pad)
#define STAGE_BYTES (PB_ROWS * XST)     // 40960
#define DEPTH 2
#define WS_BYTES (DIMD * WCOLS * 4)     // 21760
#define SMEM_DYN (DEPTH * STAGE_BYTES + WS_BYTES)  // 103680
#define PPT 16                   // points/thread in bounds part

typedef unsigned long long ull;

__device__ float g_Z[(size_t)NROWS * ZROWF];    // 8 MB, 128B rows
__device__ int   g_off[NISEG + 1];

__device__ __forceinline__ ull pack2(float lo, float hi) {
    ull r; asm("mov.b64 %0, {%1, %2};" : "=l"(r) : "f"(lo), "f"(hi)); return r;
}
__device__ __forceinline__ void unpack2(ull v, float& lo, float& hi) {
    asm("mov.b64 {%0, %1}, %2;" : "=f"(lo), "=f"(hi) : "l"(v));
}
__device__ __forceinline__ void fma2(ull& d, ull a, ull b) {
    asm("fma.rn.f32x2 %0, %1, %2, %0;" : "+l"(d) : "l"(a), "l"(b));
}
__device__ __forceinline__ void add2(ull& d, ull a) {
    asm("add.rn.f32x2 %0, %0, %1;" : "+l"(d) : "l"(a));
}
__device__ __forceinline__ void cpasync16(unsigned smem, const void* g) {
    asm volatile("cp.async.cg.shared.global [%0], [%1], 16;"
                 :: "r"(smem), "l"(g));
}
__device__ __forceinline__ void cpcommit() {
    asm volatile("cp.async.commit_group;");
}
__device__ __forceinline__ void cpwait1() {
    asm volatile("cp.async.wait_group 1;");
}

// ---------------------------------------------------------------------------
// Fat kernel: blocks [0, PROJ_BLOCKS) compute Z = X@W (coalesced cp.async,
// double-buffered, 2 rows/thread, 16 warps/SM); remaining blocks compute
// segment boundary offsets.
// ---------------------------------------------------------------------------
__global__ __launch_bounds__(THREADS)
void fat_kernel(const float* __restrict__ X, const float* __restrict__ W,
                const int* __restrict__ segs, int P) {
    extern __shared__ __align__(16) char smem[];
    float* ws = (float*)smem;                 // 21760 B
    char*  xs = smem + WS_BYTES;              // 2 stage buffers

    if (blockIdx.x < PROJ_BLOCKS) {
        const int t = threadIdx.x;
        const int row0 = blockIdx.x * PB_ROWS;
        const char* gX = (const char*)(X + (size_t)row0 * DIMD);

        // Coalesced stage issue: 512 rows x 64 B (64B-aligned: 1088 = 17*64).
        auto issue_stage = [&](int s) {
            unsigned sb = (unsigned)__cvta_generic_to_shared(xs)
                        + (unsigned)((s & 1) * STAGE_BYTES);
            const char* gbase = gX + (size_t)s * 64;
#pragma unroll
            for (int k = 0; k < 8; k++) {
                int i = t + k * THREADS;          // 0..2047
                int r = i >> 2;
                int c = i & 3;
                cpasync16(sb + (unsigned)(r * XST + c * 16),
                          gbase + (size_t)r * (DIMD * 4) + c * 16);
            }
        };

        issue_stage(0); cpcommit();
        issue_stage(1); cpcommit();

        // Stage W (padded to 20 cols) while cp.asyncs fly
        for (int i = t; i < DIMD * WCOLS; i += THREADS) {
            int dd = i / WCOLS, c = i - dd * WCOLS;
            ws[i] = (c < NC) ? W[dd * NC + c] : 0.f;
        }

        ull accA[NPAIR], accB[NPAIR];
        const ull z2 = pack2(0.f, 0.f);
#pragma unroll
        for (int j = 0; j < NPAIR; j++) { accA[j] = z2; accB[j] = z2; }

        for (int s = 0; s < NSTAGE; s++) {
            cpwait1();            // stage s resident (only newest may pend)
            __syncthreads();      // stage s + ws visible to all

            const char* sbase = xs + (s & 1) * STAGE_BYTES;
            const float4* xa = (const float4*)(sbase + t * XST);
            const float4* xb = (const float4*)(sbase + (t + 256) * XST);
            const ulonglong2* wq = (const ulonglong2*)(ws + s * SDW * WCOLS);
#pragma unroll
            for (int k = 0; k < 4; k++) {
                float4 va = xa[k];                 // LDS.128, conflict-free
                float4 vb = xb[k];
                float fa[4] = {va.x, va.y, va.z, va.w};
                float fb[4] = {vb.x, vb.y, vb.z, vb.w};
#pragma unroll
                for (int m = 0; m < 4; m++) {
                    int dd = k * 4 + m;
                    ull xaa = pack2(fa[m], fa[m]);
                    ull xbb = pack2(fb[m], fb[m]);
#pragma unroll
                    for (int jj = 0; jj < 5; jj++) {
                        ulonglong2 w = wq[dd * 5 + jj];   // LDS.128 broadcast
                        fma2(accA[2 * jj],     xaa, w.x);
                        fma2(accA[2 * jj + 1], xaa, w.y);
                        fma2(accB[2 * jj],     xbb, w.x);
                        fma2(accB[2 * jj + 1], xbb, w.y);
                    }
                }
            }

            __syncthreads();      // all reads of buffer (s&1) done
            if (s + 2 < NSTAGE) issue_stage(s + 2);
            cpcommit();           // unconditional: uniform group count
        }

        ulonglong2* za = (ulonglong2*)&g_Z[(size_t)(row0 + t) * ZROWF];
        ulonglong2* zb = (ulonglong2*)&g_Z[(size_t)(row0 + t + 256) * ZROWF];
#pragma unroll
        for (int jj = 0; jj < 5; jj++) {
            ulonglong2 sa; sa.x = accA[2 * jj]; sa.y = accA[2 * jj + 1];
            ulonglong2 sb; sb.x = accB[2 * jj]; sb.y = accB[2 * jj + 1];
            za[jj] = sa; zb[jj] = sb;
        }
    } else {
        // ----------------- segment bounds part -----------------
        const int base = (blockIdx.x - PROJ_BLOCKS) * (THREADS * PPT)
                       + threadIdx.x * PPT;
        if (base >= P) return;
        int vv[PPT];
        const int4* s4 = (const int4*)(segs + base);
#pragma unroll
        for (int q = 0; q < PPT / 4; q++) {
            int4 v = __ldg(s4 + q);
            vv[q*4+0] = v.x; vv[q*4+1] = v.y; vv[q*4+2] = v.z; vv[q*4+3] = v.w;
        }
        int prev = (base == 0) ? -1 : __ldg(segs + base - 1);
#pragma unroll
        for (int k = 0; k < PPT; k++) {
            int s = vv[k];
            if (s != prev)
                for (int q = prev + 1; q <= s; q++) g_off[q] = base + k;
            prev = s;
        }
        if (base + PPT >= P)
            for (int q = prev + 1; q <= NISEG; q++) g_off[q] = P;
    }
}

// ---------------------------------------------------------------------------
// Seg kernel: 2 warps/segment, 3 groups x 10 pair-lanes, software-pipelined
// MLP-8 (prefetch next batch's pidx while current Z loads fly).
// ---------------------------------------------------------------------------
__global__ __launch_bounds__(256)
void seg_kernel(const int* __restrict__ pidx, const float* __restrict__ bias,
                float* __restrict__ out) {
    const int t = threadIdx.x;
    const int w = t >> 5;
    const int lane = t & 31;
    const int h = w & 1;
    const int s = blockIdx.x * 4 + (w >> 1);

    const int start = __ldg(&g_off[s]);
    const int end   = __ldg(&g_off[s + 1]);

    const int g = lane / NPAIR;          // 0..2 active; lanes 30,31 idle
    const int j = lane - g * NPAIR;

    __shared__ ull sAcc[8 * NPAIR];

    ull acc0 = 0, acc1 = 0;
    if (g < 3) {
        int p = start + 3 * h + g;       // stride 6 across both warps
        if (p < end) {
            int r[8];
#pragma unroll
            for (int k = 0; k < 8; k++) {
                int q = p + 6 * k;
                r[k] = __ldg(pidx + (q < end ? q : end - 1));
            }
            while (p + 42 < end) {
                ull v[8];
#pragma unroll
                for (int k = 0; k < 8; k++)
                    v[k] = *(const ull*)&g_Z[(size_t)r[k] * ZROWF + 2 * j];
                const int pn = p + 48;
#pragma unroll
                for (int k = 0; k < 8; k++) {          // prefetch next batch
                    int q = pn + 6 * k;
                    r[k] = __ldg(pidx + (q < end ? q : end - 1));
                }
#pragma unroll
                for (int k = 0; k < 8; k++)
                    add2((k & 1) ? acc1 : acc0, v[k]);
                p = pn;
            }
            for (; p < end; p += 6) {                  // tail
                int rr = __ldg(pidx + p);
                ull v = *(const ull*)&g_Z[(size_t)rr * ZROWF + 2 * j];
                add2(acc0, v);
            }
            add2(acc0, acc1);
        }
    }

    ull v1 = __shfl_down_sync(0xffffffffu, acc0, 10);
    ull v2 = __shfl_down_sync(0xffffffffu, acc0, 20);
    add2(acc0, v1);
    add2(acc0, v2);

    if (lane < NPAIR) sAcc[w * NPAIR + lane] = acc0;
    __syncthreads();

    if (h == 0 && lane < NPAIR) {
        ull total = sAcc[w * NPAIR + lane];
        add2(total, sAcc[(w + 1) * NPAIR + lane]);
        float f0, f1; unpack2(total, f0, f1);
        float cnt = (float)(end - start);
        float inv = 1.0f / fmaxf(cnt, 1.0f);
        int c0 = 2 * lane;
        float x0 = f0 * inv + __ldg(bias + c0);
        out[(size_t)s * NC + c0] = 1.0f / (1.0f + __expf(-x0));
        if (c0 + 1 < NC) {
            float x1 = f1 * inv + __ldg(bias + c0 + 1);
            out[(size_t)s * NC + c0 + 1] = 1.0f / (1.0f + __expf(-x1));
        }
    }
}

// ---------------------------------------------------------------------------
extern "C" void kernel_launch(void* const* d_in, const int* in_sizes, int n_in,
                              void* d_out, int out_size) {
    const float* X    = (const float*)d_in[0];
    const float* W    = (const float*)d_in[1];
    const float* b    = (const float*)d_in[2];
    const int*   pidx = (const int*)d_in[3];
    const int*   segs = (const int*)d_in[4];
    float*       out  = (float*)d_out;

    const int P = in_sizes[3];
    const int boundsBlocks = (P + THREADS * PPT - 1) / (THREADS * PPT);

    static int attr_done = 0;
    if (!attr_done) {
        cudaFuncSetAttribute(fat_kernel,
                             cudaFuncAttributeMaxDynamicSharedMemorySize,
                             SMEM_DYN);
        attr_done = 1;
    }

    fat_kernel<<<PROJ_BLOCKS + boundsBlocks, THREADS, SMEM_DYN>>>(X, W, segs, P);
    seg_kernel<<<NISEG / 4, 256>>>(pidx, b, out);
}